// round 13
// baseline (speedup 1.0000x reference)
#include <cuda_runtime.h>
#include <cuda_fp16.h>
#include <stdint.h>
#include <math.h>

// ---------------- problem constants ----------------
#define CDIM    256
#define HDIM    56
#define WDIM    56
#define HW      3136
#define L_TOTAL 25088
#define DDIM    2304

// ---------------- scratch: single fp16 planes ----------------
__device__ __align__(128) __half g_t [(size_t)L_TOTAL * DDIM];
__device__ __align__(128) __half g_h [(size_t)L_TOTAL * CDIM];
__device__ __align__(128) __half g_p [(size_t)L_TOTAL * DDIM];
__device__ __align__(128) __half g_w1[(size_t)CDIM * DDIM];
__device__ __align__(128) __half g_w2[(size_t)DDIM * CDIM];
__device__ __align__(128) __half g_w3[(size_t)CDIM * DDIM];

// ---------------- helpers ----------------
__device__ __forceinline__ uint32_t smem_u32(const void* p) {
    uint32_t a;
    asm("{ .reg .u64 t; cvta.to.shared.u64 t, %1; cvt.u32.u64 %0, t; }" : "=r"(a) : "l"(p));
    return a;
}
__device__ __forceinline__ void ldm_x4(uint32_t* r, uint32_t addr) {
    asm volatile("ldmatrix.sync.aligned.m8n8.x4.shared.b16 {%0,%1,%2,%3}, [%4];"
        : "=r"(r[0]), "=r"(r[1]), "=r"(r[2]), "=r"(r[3]) : "r"(addr));
}
__device__ __forceinline__ void mma16816(float* d, const uint32_t* a, uint32_t b0, uint32_t b1) {
    asm volatile("mma.sync.aligned.m16n8k16.row.col.f32.f16.f16.f32 "
        "{%0,%1,%2,%3}, {%4,%5,%6,%7}, {%8,%9}, {%0,%1,%2,%3};"
        : "+f"(d[0]), "+f"(d[1]), "+f"(d[2]), "+f"(d[3])
        : "r"(a[0]), "r"(a[1]), "r"(a[2]), "r"(a[3]), "r"(b0), "r"(b1));
}
__device__ __forceinline__ void cp_async16(uint32_t dst, const void* src) {
    asm volatile("cp.async.cg.shared.global [%0], [%1], 16;" :: "r"(dst), "l"(src));
}
#define CP_COMMIT() asm volatile("cp.async.commit_group;" ::: "memory")
#define CP_WAIT2()  asm volatile("cp.async.wait_group 2;" ::: "memory")

// ---------------- K0: tiled unfold -> fp16 plane ----------------
__global__ __launch_bounds__(256) void unfold_tiled(const float* __restrict__ x,
    __half* __restrict__ t)
{
    __shared__ __half xs[64 * 3 * 58];
    const int chunk = blockIdx.x;
    const int h     = blockIdx.y;
    const int b     = blockIdx.z;
    const int c0    = chunk * 64;
    const int tid   = threadIdx.x;

    for (int i = tid; i < 64 * 3; i += 256) {
        xs[i * 58 + 0]  = __float2half(0.f);
        xs[i * 58 + 57] = __float2half(0.f);
    }
    for (int i = tid; i < 64 * 3 * 56; i += 256) {
        int w = i % 56;
        int rest = i / 56;
        int hh = rest % 3;
        int c  = rest / 3;
        int gh = h + hh - 1;
        float v = 0.f;
        if (gh >= 0 && gh < HDIM)
            v = x[((size_t)(b * CDIM + c0 + c) * HDIM + gh) * WDIM + w];
        xs[(c * 3 + hh) * 58 + (w + 1)] = __float2half(v);
    }
    __syncthreads();

    const int lbase = b * HW + h * WDIM;
    for (int pid = tid; pid < 56 * 288; pid += 256) {
        int j = pid % 288;
        int w = pid / 288;
        int e0 = 2 * j;
        __half v0, v1;
        {
            int e = e0;
            int c = e / 9, r = e - 9 * c;
            int di = r / 3, dj = r - 3 * di;
            v0 = xs[(c * 3 + di) * 58 + (w + dj)];
        }
        {
            int e = e0 + 1;
            int c = e / 9, r = e - 9 * c;
            int di = r / 3, dj = r - 3 * di;
            v1 = xs[(c * 3 + di) * 58 + (w + dj)];
        }
        __half2 o; o.x = v0; o.y = v1;
        *(__half2*)(t + (size_t)(lbase + w) * DDIM + chunk * 576 + e0) = o;
    }
}

// ---------------- fused weight transpose ----------------
__global__ __launch_bounds__(256) void wtrans_all(
    const float* __restrict__ W1, const float* __restrict__ W2, const float* __restrict__ W3,
    __half* __restrict__ o1, __half* __restrict__ o2, __half* __restrict__ o3)
{
    const int seg = blockIdx.x / 1152;
    const int blk = blockIdx.x % 1152;
    const float* W = (seg == 0) ? W1 : (seg == 1) ? W2 : W3;
    __half* o      = (seg == 0) ? o1 : (seg == 1) ? o2 : o3;
    const int K    = (seg == 1) ? CDIM : DDIM;
    const int N    = (seg == 1) ? DDIM : CDIM;

    int t = blk * 256 + threadIdx.x;
    int NP = N * (K / 2);
    if (t >= NP) return;
    int kp = t % (K / 2), n = t / (K / 2);
    int k0 = kp * 2;
    __half2 h2;
    h2.x = __float2half(W[(size_t)k0 * N + n]);
    h2.y = __float2half(W[(size_t)(k0 + 1) * N + n]);
    *(__half2*)(o + (size_t)n * K + k0) = h2;
}

// ---------------- pipelined fp16 mma.sync GEMM: BK=64 stages ----------------
// Stage layout: [A k-sub0 8KB][A k-sub1 8KB][B k-sub0 8KB][B k-sub1 8KB] = 32KB.
// Each sub-plane is the proven BK=32 64B-row chunk-swizzled layout.
// BM=128 BN=128, 256 threads, warps 4m x 2n, 3 stages.
// MODE 1: relu -> fp16   MODE 2: sigmoid * X -> fp16   MODE 3: fp32 + bias
#define STAGE_B 32768
#define NSTAGE  3
#define SMEM_BYTES (NSTAGE * STAGE_B)

template<int MODE>
__global__ __launch_bounds__(256, 2) void gemm_mma(
    const __half* __restrict__ A, const __half* __restrict__ B,
    const float* __restrict__ bias,
    const __half* __restrict__ X,
    __half* __restrict__ Oh, float* __restrict__ Of,
    int M, int N, int Kd)
{
    extern __shared__ __align__(128) char smem[];
    const uint32_t sb = smem_u32(smem);

    const int tid  = threadIdx.x;
    const int lane = tid & 31;
    const int wid  = tid >> 5;
    const int warp_m = wid & 3;
    const int warp_n = wid >> 2;
    const int m0 = blockIdx.y * 128;
    const int n0 = blockIdx.x * 128;

    const int lr = tid >> 2;
    const int lc = tid & 3;

    float acc[2][8][4];
    #pragma unroll
    for (int a = 0; a < 2; a++)
        #pragma unroll
        for (int b = 0; b < 8; b++)
            #pragma unroll
            for (int c = 0; c < 4; c++) acc[a][b][c] = 0.f;

    // precomputed ldmatrix offsets: row-offset + swizzled column, fused.
    const int grp = lane >> 3, r8 = lane & 7;
    const int rowoff = ((grp & 1) << 3) + r8;
    const int cg = grp >> 1;
    uint32_t preA[2][2], preB[4][2];
    #pragma unroll
    for (int tm = 0; tm < 2; tm++) {
        int r = warp_m * 32 + tm * 16 + rowoff;
        int sw = (r >> 1) & 3;
        #pragma unroll
        for (int kk = 0; kk < 2; kk++)
            preA[tm][kk] = (uint32_t)(r * 64 + ((((kk << 1) | cg) ^ sw) << 4));
    }
    #pragma unroll
    for (int p = 0; p < 4; p++) {
        int r = warp_n * 64 + p * 16 + rowoff;
        int sw = (r >> 1) & 3;
        #pragma unroll
        for (int kk = 0; kk < 2; kk++)
            preB[p][kk] = (uint32_t)(r * 64 + ((((kk << 1) | cg) ^ sw) << 4));
    }

    const int NIT = Kd >> 6;   // BK=64

    auto load_stage = [&](int st, int k0) {
        uint32_t stb = sb + st * STAGE_B;
        #pragma unroll
        for (int i = 0; i < 8; i++) {
            int plane = i >> 1;                  // 0:A0 1:A1 2:B0 3:B1
            int r = ((i & 1) << 6) + lr;
            uint32_t dst = stb + plane * 8192 + r * 64 + ((lc ^ ((r >> 1) & 3)) << 4);
            int ko = k0 + ((plane & 1) << 5);    // +32 for sub1
            const char* src = (plane < 2)
                ? (const char*)(A + (size_t)(m0 + r) * Kd + ko + lc * 8)
                : (const char*)(B + (size_t)(n0 + r) * Kd + ko + lc * 8);
            cp_async16(dst, src);
        }
    };

    #pragma unroll
    for (int s = 0; s < NSTAGE; s++) {
        load_stage(s, s * 64);
        CP_COMMIT();
    }

    for (int it = 0; it < NIT; it++) {
        CP_WAIT2();
        __syncthreads();
        const int st = it % NSTAGE;
        const uint32_t stb = sb + st * STAGE_B;

        #pragma unroll
        for (int ks = 0; ks < 4; ks++) {
            const uint32_t aB = stb + ((ks & 2) ? 8192 : 0);
            const uint32_t bB = stb + 16384 + ((ks & 2) ? 8192 : 0);
            const int kk = ks & 1;
            uint32_t ah[2][4], bh[4][4];
            #pragma unroll
            for (int tm = 0; tm < 2; tm++)
                ldm_x4(ah[tm], aB + preA[tm][kk]);
            #pragma unroll
            for (int p = 0; p < 4; p++)
                ldm_x4(bh[p], bB + preB[p][kk]);
            #pragma unroll
            for (int tm = 0; tm < 2; tm++)
                #pragma unroll
                for (int tn = 0; tn < 8; tn++) {
                    int p = tn >> 1, o = tn & 1;
                    mma16816(acc[tm][tn], ah[tm], bh[p][o], bh[p][2 + o]);
                }
        }
        __syncthreads();

        int nxt = it + NSTAGE;
        if (nxt < NIT) load_stage(st, nxt * 64);
        CP_COMMIT();
    }

    // ---------------- epilogue ----------------
    const int qr = lane >> 2;
    const int qc = (lane & 3) * 2;
    #pragma unroll
    for (int tm = 0; tm < 2; tm++) {
        int mb = m0 + warp_m * 32 + tm * 16;
        #pragma unroll
        for (int tn = 0; tn < 8; tn++) {
            int n = n0 + warp_n * 64 + tn * 8 + qc;
            float bx = bias[n], by = bias[n + 1];
            #pragma unroll
            for (int half = 0; half < 2; half++) {
                int m = mb + qr + half * 8;
                float vx = acc[tm][tn][half * 2 + 0] + bx;
                float vy = acc[tm][tn][half * 2 + 1] + by;
                size_t o = (size_t)m * N + n;
                if (MODE == 1) {
                    __half2 w;
                    w.x = __float2half(fmaxf(vx, 0.f));
                    w.y = __float2half(fmaxf(vy, 0.f));
                    *(__half2*)(Oh + o) = w;
                } else if (MODE == 2) {
                    float sx = 1.f / (1.f + __expf(-vx));
                    float sy = 1.f / (1.f + __expf(-vy));
                    __half2 tv = *(const __half2*)(X + o);
                    __half2 w;
                    w.x = __float2half(__half2float(tv.x) * sx);
                    w.y = __float2half(__half2float(tv.y) * sy);
                    *(__half2*)(Oh + o) = w;
                } else {
                    float2 w; w.x = vx; w.y = vy;
                    *(float2*)(Of + o) = w;
                }
            }
        }
    }
}

// ---------------- host launch ----------------
extern "C" void kernel_launch(void* const* d_in, const int* in_sizes, int n_in,
                              void* d_out, int out_size)
{
    const float* x  = (const float*)d_in[0];
    const float* W1 = (const float*)d_in[1];
    const float* b1 = (const float*)d_in[2];
    const float* W2 = (const float*)d_in[3];
    const float* b2 = (const float*)d_in[4];
    const float* W3 = (const float*)d_in[5];
    const float* b3 = (const float*)d_in[6];
    float* out = (float*)d_out;

    __half *pt, *ph, *pp, *w1, *w2, *w3;
    cudaGetSymbolAddress((void**)&pt, g_t);
    cudaGetSymbolAddress((void**)&ph, g_h);
    cudaGetSymbolAddress((void**)&pp, g_p);
    cudaGetSymbolAddress((void**)&w1, g_w1);
    cudaGetSymbolAddress((void**)&w2, g_w2);
    cudaGetSymbolAddress((void**)&w3, g_w3);

    cudaFuncSetAttribute(gemm_mma<1>, cudaFuncAttributeMaxDynamicSharedMemorySize, SMEM_BYTES);
    cudaFuncSetAttribute(gemm_mma<2>, cudaFuncAttributeMaxDynamicSharedMemorySize, SMEM_BYTES);
    cudaFuncSetAttribute(gemm_mma<3>, cudaFuncAttributeMaxDynamicSharedMemorySize, SMEM_BYTES);

    unfold_tiled<<<dim3(4, 56, 8), 256>>>(x, pt);
    wtrans_all<<<3 * 1152, 256>>>(W1, W2, W3, w1, w2, w3);

    // K1: h = relu(t @ W1 + b1)        [25088 x 256],  K=2304
    gemm_mma<1><<<dim3(CDIM / 128, L_TOTAL / 128), 256, SMEM_BYTES>>>(
        pt, w1, b1, nullptr, ph, nullptr, L_TOTAL, CDIM, DDIM);
    // K2: p = t * sigmoid(h @ W2 + b2) [25088 x 2304], K=256
    gemm_mma<2><<<dim3(DDIM / 128, L_TOTAL / 128), 256, SMEM_BYTES>>>(
        ph, w2, b2, pt, pp, nullptr, L_TOTAL, DDIM, CDIM);
    // K3: out = p @ W3 + b3            [25088 x 256],  K=2304
    gemm_mma<3><<<dim3(CDIM / 128, L_TOTAL / 128), 256, SMEM_BYTES>>>(
        pp, w3, b3, nullptr, nullptr, out, L_TOTAL, CDIM, DDIM);
}

// round 14
// speedup vs baseline: 1.0106x; 1.0106x over previous
#include <cuda_runtime.h>
#include <cuda_fp16.h>
#include <stdint.h>
#include <math.h>

// ---------------- problem constants ----------------
#define CDIM    256
#define HDIM    56
#define WDIM    56
#define HW      3136
#define L_TOTAL 25088
#define DDIM    2304

// ---------------- scratch: single fp16 planes ----------------
__device__ __align__(128) __half g_t [(size_t)L_TOTAL * DDIM];
__device__ __align__(128) __half g_h [(size_t)L_TOTAL * CDIM];
__device__ __align__(128) __half g_p [(size_t)L_TOTAL * DDIM];
__device__ __align__(128) __half g_w1[(size_t)CDIM * DDIM];
__device__ __align__(128) __half g_w2[(size_t)DDIM * CDIM];
__device__ __align__(128) __half g_w3[(size_t)CDIM * DDIM];

// ---------------- helpers ----------------
__device__ __forceinline__ uint32_t smem_u32(const void* p) {
    uint32_t a;
    asm("{ .reg .u64 t; cvta.to.shared.u64 t, %1; cvt.u32.u64 %0, t; }" : "=r"(a) : "l"(p));
    return a;
}
__device__ __forceinline__ void ldm_x4(uint32_t* r, uint32_t addr) {
    asm volatile("ldmatrix.sync.aligned.m8n8.x4.shared.b16 {%0,%1,%2,%3}, [%4];"
        : "=r"(r[0]), "=r"(r[1]), "=r"(r[2]), "=r"(r[3]) : "r"(addr));
}
__device__ __forceinline__ void mma16816(float* d, const uint32_t* a, uint32_t b0, uint32_t b1) {
    asm volatile("mma.sync.aligned.m16n8k16.row.col.f32.f16.f16.f32 "
        "{%0,%1,%2,%3}, {%4,%5,%6,%7}, {%8,%9}, {%0,%1,%2,%3};"
        : "+f"(d[0]), "+f"(d[1]), "+f"(d[2]), "+f"(d[3])
        : "r"(a[0]), "r"(a[1]), "r"(a[2]), "r"(a[3]), "r"(b0), "r"(b1));
}
__device__ __forceinline__ void cp_async16(uint32_t dst, const void* src) {
    asm volatile("cp.async.cg.shared.global [%0], [%1], 16;" :: "r"(dst), "l"(src));
}
#define CP_COMMIT() asm volatile("cp.async.commit_group;" ::: "memory")
#define CP_WAIT2()  asm volatile("cp.async.wait_group 2;" ::: "memory")

// ---------------- K0: tiled unfold -> fp16 plane ----------------
__global__ __launch_bounds__(256) void unfold_tiled(const float* __restrict__ x,
    __half* __restrict__ t)
{
    __shared__ __half xs[64 * 3 * 58];
    const int chunk = blockIdx.x;
    const int h     = blockIdx.y;
    const int b     = blockIdx.z;
    const int c0    = chunk * 64;
    const int tid   = threadIdx.x;

    for (int i = tid; i < 64 * 3; i += 256) {
        xs[i * 58 + 0]  = __float2half(0.f);
        xs[i * 58 + 57] = __float2half(0.f);
    }
    for (int i = tid; i < 64 * 3 * 56; i += 256) {
        int w = i % 56;
        int rest = i / 56;
        int hh = rest % 3;
        int c  = rest / 3;
        int gh = h + hh - 1;
        float v = 0.f;
        if (gh >= 0 && gh < HDIM)
            v = x[((size_t)(b * CDIM + c0 + c) * HDIM + gh) * WDIM + w];
        xs[(c * 3 + hh) * 58 + (w + 1)] = __float2half(v);
    }
    __syncthreads();

    const int lbase = b * HW + h * WDIM;
    for (int pid = tid; pid < 56 * 288; pid += 256) {
        int j = pid % 288;
        int w = pid / 288;
        int e0 = 2 * j;
        __half v0, v1;
        {
            int e = e0;
            int c = e / 9, r = e - 9 * c;
            int di = r / 3, dj = r - 3 * di;
            v0 = xs[(c * 3 + di) * 58 + (w + dj)];
        }
        {
            int e = e0 + 1;
            int c = e / 9, r = e - 9 * c;
            int di = r / 3, dj = r - 3 * di;
            v1 = xs[(c * 3 + di) * 58 + (w + dj)];
        }
        __half2 o; o.x = v0; o.y = v1;
        *(__half2*)(t + (size_t)(lbase + w) * DDIM + chunk * 576 + e0) = o;
    }
}

// ---------------- fused weight transpose ----------------
__global__ __launch_bounds__(256) void wtrans_all(
    const float* __restrict__ W1, const float* __restrict__ W2, const float* __restrict__ W3,
    __half* __restrict__ o1, __half* __restrict__ o2, __half* __restrict__ o3)
{
    const int seg = blockIdx.x / 1152;
    const int blk = blockIdx.x % 1152;
    const float* W = (seg == 0) ? W1 : (seg == 1) ? W2 : W3;
    __half* o      = (seg == 0) ? o1 : (seg == 1) ? o2 : o3;
    const int K    = (seg == 1) ? CDIM : DDIM;
    const int N    = (seg == 1) ? DDIM : CDIM;

    int t = blk * 256 + threadIdx.x;
    int NP = N * (K / 2);
    if (t >= NP) return;
    int kp = t % (K / 2), n = t / (K / 2);
    int k0 = kp * 2;
    __half2 h2;
    h2.x = __float2half(W[(size_t)k0 * N + n]);
    h2.y = __float2half(W[(size_t)(k0 + 1) * N + n]);
    *(__half2*)(o + (size_t)n * K + k0) = h2;
}

// ---------------- R12-exact pipelined fp16 GEMM (K1 / K3) ----------------
// BM=128 BN=128 BK=32, 256 threads, 3-stage cp.async, warps 4m x 2n.
// MODE 1: relu -> fp16   MODE 3: fp32 + bias
#define STAGE_B 16384
#define NSTAGE  3
#define SMEM_BYTES (NSTAGE * STAGE_B)

template<int MODE>
__global__ __launch_bounds__(256, 2) void gemm_mma(
    const __half* __restrict__ A, const __half* __restrict__ B,
    const float* __restrict__ bias,
    __half* __restrict__ Oh, float* __restrict__ Of,
    int M, int N, int Kd)
{
    extern __shared__ __align__(128) char smem[];
    const uint32_t sb = smem_u32(smem);

    const int tid  = threadIdx.x;
    const int lane = tid & 31;
    const int wid  = tid >> 5;
    const int warp_m = wid & 3;
    const int warp_n = wid >> 2;
    const int m0 = blockIdx.y * 128;
    const int n0 = blockIdx.x * 128;

    const int lr = tid >> 2;
    const int lc = tid & 3;

    float acc[2][8][4];
    #pragma unroll
    for (int a = 0; a < 2; a++)
        #pragma unroll
        for (int b = 0; b < 8; b++)
            #pragma unroll
            for (int c = 0; c < 4; c++) acc[a][b][c] = 0.f;

    const int grp = lane >> 3, r8 = lane & 7;
    const int rowoff = ((grp & 1) << 3) + r8;
    const int cg = grp >> 1;
    int offA[2], swA[2], offB[4], swB[4];
    #pragma unroll
    for (int tm = 0; tm < 2; tm++) {
        int r = warp_m * 32 + tm * 16 + rowoff;
        offA[tm] = r * 64; swA[tm] = (r >> 1) & 3;
    }
    #pragma unroll
    for (int p = 0; p < 4; p++) {
        int r = warp_n * 64 + p * 16 + rowoff;
        offB[p] = r * 64; swB[p] = (r >> 1) & 3;
    }

    const int NIT = Kd >> 5;

    auto load_stage = [&](int st, int k0) {
        uint32_t stb = sb + st * STAGE_B;
        #pragma unroll
        for (int i = 0; i < 4; i++) {
            int plane = i >> 1;
            int r = ((i & 1) << 6) + lr;
            uint32_t dst = stb + plane * 8192 + r * 64 + ((lc ^ ((r >> 1) & 3)) << 4);
            const char* src = (plane == 0)
                ? (const char*)(A + (size_t)(m0 + r) * Kd + k0 + lc * 8)
                : (const char*)(B + (size_t)(n0 + r) * Kd + k0 + lc * 8);
            cp_async16(dst, src);
        }
    };

    #pragma unroll
    for (int s = 0; s < NSTAGE; s++) {
        load_stage(s, s * 32);
        CP_COMMIT();
    }

    for (int it = 0; it < NIT; it++) {
        CP_WAIT2();
        __syncthreads();
        const int st = it % NSTAGE;
        const uint32_t stb = sb + st * STAGE_B;

        #pragma unroll
        for (int ks = 0; ks < 2; ks++) {
            uint32_t ah[2][4], bh[4][4];
            #pragma unroll
            for (int tm = 0; tm < 2; tm++) {
                uint32_t colA = (uint32_t)((((ks << 1) | cg) ^ swA[tm]) << 4);
                ldm_x4(ah[tm], stb + offA[tm] + colA);
            }
            #pragma unroll
            for (int p = 0; p < 4; p++) {
                uint32_t colB = (uint32_t)((((ks << 1) | cg) ^ swB[p]) << 4);
                ldm_x4(bh[p], stb + 8192 + offB[p] + colB);
            }
            #pragma unroll
            for (int tm = 0; tm < 2; tm++)
                #pragma unroll
                for (int tn = 0; tn < 8; tn++) {
                    int p = tn >> 1, o = tn & 1;
                    mma16816(acc[tm][tn], ah[tm], bh[p][o], bh[p][2 + o]);
                }
        }
        __syncthreads();

        int nxt = it + NSTAGE;
        if (nxt < NIT) load_stage(st, nxt * 32);
        CP_COMMIT();
    }

    const int qr = lane >> 2;
    const int qc = (lane & 3) * 2;
    #pragma unroll
    for (int tm = 0; tm < 2; tm++) {
        int mb = m0 + warp_m * 32 + tm * 16;
        #pragma unroll
        for (int tn = 0; tn < 8; tn++) {
            int n = n0 + warp_n * 64 + tn * 8 + qc;
            float bx = bias[n], by = bias[n + 1];
            #pragma unroll
            for (int half = 0; half < 2; half++) {
                int m = mb + qr + half * 8;
                float vx = acc[tm][tn][half * 2 + 0] + bx;
                float vy = acc[tm][tn][half * 2 + 1] + by;
                size_t o = (size_t)m * N + n;
                if (MODE == 1) {
                    __half2 w;
                    w.x = __float2half(fmaxf(vx, 0.f));
                    w.y = __float2half(fmaxf(vy, 0.f));
                    *(__half2*)(Oh + o) = w;
                } else {
                    float2 w; w.x = vx; w.y = vy;
                    *(float2*)(Of + o) = w;
                }
            }
        }
    }
}

// ---------------- K2 strip kernel: [128 x 768] per CTA ----------------
// A = h[128,256] fully resident in smem (8 BK=32 sub-planes, 64KB).
// B = w2 streamed through 3x8KB stages, pipeline continuous across 6 n-tiles.
// Epilogue per n-tile: p = t * sigmoid(acc + b2) -> fp16.
#define K2_NT    6
#define K2_KD    256
#define K2_NITT  8                         // iters per n-tile (K=256 / 32)
#define K2_TOT   (K2_NT * K2_NITT)         // 48
#define K2_ABYTES 65536
#define K2_SMEM  (K2_ABYTES + 3 * 8192)    // 90112

__global__ __launch_bounds__(256, 2) void gemm_k2(
    const __half* __restrict__ A, const __half* __restrict__ B,
    const float* __restrict__ bias,
    const __half* __restrict__ X,
    __half* __restrict__ Oh, int N)
{
    extern __shared__ __align__(128) char smem[];
    const uint32_t sb = smem_u32(smem);

    const int tid  = threadIdx.x;
    const int lane = tid & 31;
    const int wid  = tid >> 5;
    const int warp_m = wid & 3;
    const int warp_n = wid >> 2;
    const int m0 = blockIdx.y * 128;
    const int n_base = blockIdx.x * (K2_NT * 128);

    const int lr = tid >> 2;
    const int lc = tid & 3;

    const int grp = lane >> 3, r8 = lane & 7;
    const int rowoff = ((grp & 1) << 3) + r8;
    const int cg = grp >> 1;
    int offA[2], swA[2], offB[4], swB[4];
    #pragma unroll
    for (int tm = 0; tm < 2; tm++) {
        int r = warp_m * 32 + tm * 16 + rowoff;
        offA[tm] = r * 64; swA[tm] = (r >> 1) & 3;
    }
    #pragma unroll
    for (int p = 0; p < 4; p++) {
        int r = warp_n * 64 + p * 16 + rowoff;
        offB[p] = r * 64; swB[p] = (r >> 1) & 3;
    }

    // ---- load A fully: 128 rows x 256 halves -> 8 sub-planes of 8KB ----
    // 4096 16B-chunks; chunk c within row: sub-plane ks = c>>2, col = c&3.
    #pragma unroll
    for (int pass = 0; pass < 16; pass++) {
        int idx = pass * 256 + tid;
        int row = idx >> 5;
        int cic = idx & 31;
        int ks  = cic >> 2;
        int c   = cic & 3;
        uint32_t dst = sb + ks * 8192 + row * 64 + ((c ^ ((row >> 1) & 3)) << 4);
        cp_async16(dst, (const char*)(A + (size_t)(m0 + row) * K2_KD + ks * 32 + c * 8));
    }
    CP_COMMIT();

    // ---- B stage loader: global stage gs -> buffer gs%3 ----
    auto load_bstage = [&](int gs) {
        int nt = gs >> 3, ksub = gs & 7;
        int n0 = n_base + nt * 128;
        uint32_t stb = sb + K2_ABYTES + (gs % 3) * 8192;
        #pragma unroll
        for (int i = 0; i < 2; i++) {
            int r = (i << 6) + lr;
            uint32_t dst = stb + r * 64 + ((lc ^ ((r >> 1) & 3)) << 4);
            cp_async16(dst, (const char*)(B + (size_t)(n0 + r) * K2_KD + ksub * 32 + lc * 8));
        }
    };

    #pragma unroll
    for (int s = 0; s < 3; s++) {
        load_bstage(s);
        CP_COMMIT();
    }

    const int qr = lane >> 2;
    const int qc = (lane & 3) * 2;

    for (int nt = 0; nt < K2_NT; nt++) {
        float acc[2][8][4];
        #pragma unroll
        for (int a = 0; a < 2; a++)
            #pragma unroll
            for (int b = 0; b < 8; b++)
                #pragma unroll
                for (int c = 0; c < 4; c++) acc[a][b][c] = 0.f;

        for (int it = 0; it < K2_NITT; it++) {
            const int gs = nt * K2_NITT + it;
            CP_WAIT2();
            __syncthreads();
            const uint32_t aB = sb + it * 8192;                     // A sub-plane
            const uint32_t bB = sb + K2_ABYTES + (gs % 3) * 8192;   // B stage

            #pragma unroll
            for (int ks = 0; ks < 2; ks++) {
                uint32_t ah[2][4], bh[4][4];
                #pragma unroll
                for (int tm = 0; tm < 2; tm++) {
                    uint32_t colA = (uint32_t)((((ks << 1) | cg) ^ swA[tm]) << 4);
                    ldm_x4(ah[tm], aB + offA[tm] + colA);
                }
                #pragma unroll
                for (int p = 0; p < 4; p++) {
                    uint32_t colB = (uint32_t)((((ks << 1) | cg) ^ swB[p]) << 4);
                    ldm_x4(bh[p], bB + offB[p] + colB);
                }
                #pragma unroll
                for (int tm = 0; tm < 2; tm++)
                    #pragma unroll
                    for (int tn = 0; tn < 8; tn++) {
                        int p = tn >> 1, o = tn & 1;
                        mma16816(acc[tm][tn], ah[tm], bh[p][o], bh[p][2 + o]);
                    }
            }
            __syncthreads();

            int pgs = gs + 3;
            if (pgs < K2_TOT) load_bstage(pgs);
            CP_COMMIT();
        }

        // ---- epilogue for this n-tile ----
        const int n0 = n_base + nt * 128;
        #pragma unroll
        for (int tm = 0; tm < 2; tm++) {
            int mb = m0 + warp_m * 32 + tm * 16;
            #pragma unroll
            for (int tn = 0; tn < 8; tn++) {
                int n = n0 + warp_n * 64 + tn * 8 + qc;
                float bx = bias[n], by = bias[n + 1];
                #pragma unroll
                for (int half = 0; half < 2; half++) {
                    int m = mb + qr + half * 8;
                    float vx = acc[tm][tn][half * 2 + 0] + bx;
                    float vy = acc[tm][tn][half * 2 + 1] + by;
                    float sx = 1.f / (1.f + __expf(-vx));
                    float sy = 1.f / (1.f + __expf(-vy));
                    size_t o = (size_t)m * N + n;
                    __half2 tv = *(const __half2*)(X + o);
                    __half2 w;
                    w.x = __float2half(__half2float(tv.x) * sx);
                    w.y = __float2half(__half2float(tv.y) * sy);
                    *(__half2*)(Oh + o) = w;
                }
            }
        }
    }
}

// ---------------- host launch ----------------
extern "C" void kernel_launch(void* const* d_in, const int* in_sizes, int n_in,
                              void* d_out, int out_size)
{
    const float* x  = (const float*)d_in[0];
    const float* W1 = (const float*)d_in[1];
    const float* b1 = (const float*)d_in[2];
    const float* W2 = (const float*)d_in[3];
    const float* b2 = (const float*)d_in[4];
    const float* W3 = (const float*)d_in[5];
    const float* b3 = (const float*)d_in[6];
    float* out = (float*)d_out;

    __half *pt, *ph, *pp, *w1, *w2, *w3;
    cudaGetSymbolAddress((void**)&pt, g_t);
    cudaGetSymbolAddress((void**)&ph, g_h);
    cudaGetSymbolAddress((void**)&pp, g_p);
    cudaGetSymbolAddress((void**)&w1, g_w1);
    cudaGetSymbolAddress((void**)&w2, g_w2);
    cudaGetSymbolAddress((void**)&w3, g_w3);

    cudaFuncSetAttribute(gemm_mma<1>, cudaFuncAttributeMaxDynamicSharedMemorySize, SMEM_BYTES);
    cudaFuncSetAttribute(gemm_mma<3>, cudaFuncAttributeMaxDynamicSharedMemorySize, SMEM_BYTES);
    cudaFuncSetAttribute(gemm_k2,     cudaFuncAttributeMaxDynamicSharedMemorySize, K2_SMEM);

    unfold_tiled<<<dim3(4, 56, 8), 256>>>(x, pt);
    wtrans_all<<<3 * 1152, 256>>>(W1, W2, W3, w1, w2, w3);

    // K1: h = relu(t @ W1 + b1)        [25088 x 256],  K=2304
    gemm_mma<1><<<dim3(CDIM / 128, L_TOTAL / 128), 256, SMEM_BYTES>>>(
        pt, w1, b1, ph, nullptr, L_TOTAL, CDIM, DDIM);
    // K2: p = t * sigmoid(h @ W2 + b2) [25088 x 2304], K=256 — strip kernel
    gemm_k2<<<dim3(DDIM / (K2_NT * 128), L_TOTAL / 128), 256, K2_SMEM>>>(
        ph, w2, b2, pt, pp, DDIM);
    // K3: out = p @ W3 + b3            [25088 x 256],  K=2304
    gemm_mma<3><<<dim3(CDIM / 128, L_TOTAL / 128), 256, SMEM_BYTES>>>(
        pp, w3, b3, nullptr, out, L_TOTAL, CDIM, DDIM);
}

// round 16
// speedup vs baseline: 1.1057x; 1.0941x over previous
#include <cuda_runtime.h>
#include <cuda_fp16.h>
#include <stdint.h>
#include <math.h>

// ---------------- problem constants ----------------
#define CDIM    256
#define HDIM    56
#define WDIM    56
#define HW      3136
#define L_TOTAL 25088
#define DDIM    2304

// ---------------- scratch: single fp16 planes ----------------
__device__ __align__(128) __half g_t [(size_t)L_TOTAL * DDIM];
__device__ __align__(128) __half g_h [(size_t)L_TOTAL * CDIM];
__device__ __align__(128) __half g_p [(size_t)L_TOTAL * DDIM];
__device__ __align__(128) __half g_w1[(size_t)CDIM * DDIM];
__device__ __align__(128) __half g_w2[(size_t)DDIM * CDIM];
__device__ __align__(128) __half g_w3[(size_t)CDIM * DDIM];

// ---------------- helpers ----------------
__device__ __forceinline__ uint32_t smem_u32(const void* p) {
    uint32_t a;
    asm("{ .reg .u64 t; cvta.to.shared.u64 t, %1; cvt.u32.u64 %0, t; }" : "=r"(a) : "l"(p));
    return a;
}
__device__ __forceinline__ void ldm_x4(uint32_t* r, uint32_t addr) {
    asm volatile("ldmatrix.sync.aligned.m8n8.x4.shared.b16 {%0,%1,%2,%3}, [%4];"
        : "=r"(r[0]), "=r"(r[1]), "=r"(r[2]), "=r"(r[3]) : "r"(addr));
}
__device__ __forceinline__ void mma16816(float* d, const uint32_t* a, uint32_t b0, uint32_t b1) {
    asm volatile("mma.sync.aligned.m16n8k16.row.col.f32.f16.f16.f32 "
        "{%0,%1,%2,%3}, {%4,%5,%6,%7}, {%8,%9}, {%0,%1,%2,%3};"
        : "+f"(d[0]), "+f"(d[1]), "+f"(d[2]), "+f"(d[3])
        : "r"(a[0]), "r"(a[1]), "r"(a[2]), "r"(a[3]), "r"(b0), "r"(b1));
}
__device__ __forceinline__ void cp_async16(uint32_t dst, const void* src) {
    asm volatile("cp.async.cg.shared.global [%0], [%1], 16;" :: "r"(dst), "l"(src));
}
#define CP_COMMIT() asm volatile("cp.async.commit_group;" ::: "memory")
#define CP_WAIT2()  asm volatile("cp.async.wait_group 2;" ::: "memory")
#define CP_WAIT0()  asm volatile("cp.async.wait_group 0;" ::: "memory")

// ---------------- K0: tiled unfold -> fp16 plane ----------------
__global__ __launch_bounds__(256) void unfold_tiled(const float* __restrict__ x,
    __half* __restrict__ t)
{
    __shared__ __half xs[64 * 3 * 58];
    const int chunk = blockIdx.x;
    const int h     = blockIdx.y;
    const int b     = blockIdx.z;
    const int c0    = chunk * 64;
    const int tid   = threadIdx.x;

    for (int i = tid; i < 64 * 3; i += 256) {
        xs[i * 58 + 0]  = __float2half(0.f);
        xs[i * 58 + 57] = __float2half(0.f);
    }
    for (int i = tid; i < 64 * 3 * 56; i += 256) {
        int w = i % 56;
        int rest = i / 56;
        int hh = rest % 3;
        int c  = rest / 3;
        int gh = h + hh - 1;
        float v = 0.f;
        if (gh >= 0 && gh < HDIM)
            v = x[((size_t)(b * CDIM + c0 + c) * HDIM + gh) * WDIM + w];
        xs[(c * 3 + hh) * 58 + (w + 1)] = __float2half(v);
    }
    __syncthreads();

    const int lbase = b * HW + h * WDIM;
    for (int pid = tid; pid < 56 * 288; pid += 256) {
        int j = pid % 288;
        int w = pid / 288;
        int e0 = 2 * j;
        __half v0, v1;
        {
            int e = e0;
            int c = e / 9, r = e - 9 * c;
            int di = r / 3, dj = r - 3 * di;
            v0 = xs[(c * 3 + di) * 58 + (w + dj)];
        }
        {
            int e = e0 + 1;
            int c = e / 9, r = e - 9 * c;
            int di = r / 3, dj = r - 3 * di;
            v1 = xs[(c * 3 + di) * 58 + (w + dj)];
        }
        __half2 o; o.x = v0; o.y = v1;
        *(__half2*)(t + (size_t)(lbase + w) * DDIM + chunk * 576 + e0) = o;
    }
}

// ---------------- fused weight transpose ----------------
__global__ __launch_bounds__(256) void wtrans_all(
    const float* __restrict__ W1, const float* __restrict__ W2, const float* __restrict__ W3,
    __half* __restrict__ o1, __half* __restrict__ o2, __half* __restrict__ o3)
{
    const int seg = blockIdx.x / 1152;
    const int blk = blockIdx.x % 1152;
    const float* W = (seg == 0) ? W1 : (seg == 1) ? W2 : W3;
    __half* o      = (seg == 0) ? o1 : (seg == 1) ? o2 : o3;
    const int K    = (seg == 1) ? CDIM : DDIM;
    const int N    = (seg == 1) ? DDIM : CDIM;

    int t = blk * 256 + threadIdx.x;
    int NP = N * (K / 2);
    if (t >= NP) return;
    int kp = t % (K / 2), n = t / (K / 2);
    int k0 = kp * 2;
    __half2 h2;
    h2.x = __float2half(W[(size_t)k0 * N + n]);
    h2.y = __float2half(W[(size_t)(k0 + 1) * N + n]);
    *(__half2*)(o + (size_t)n * K + k0) = h2;
}

// ---------------- pipelined fp16 mma.sync GEMM (R12 + X-prefetch) ----------------
// C = epi(A @ B^T + bias); A [M,K] fp16, B [N,K] fp16.
// BM=128 BN=128 BK=32, 256 threads, 3-stage cp.async, warps 4m x 2n.
// MODE 1: relu -> fp16
// MODE 2: sigmoid * X -> fp16; X tile (32KB) prefetched into smem during mainloop
// MODE 3: fp32 + bias
#define STAGE_B 16384
#define NSTAGE  3
#define XBUF_OFF (NSTAGE * STAGE_B)        // 49152
#define SMEM_BYTES   (NSTAGE * STAGE_B)
#define SMEM2_BYTES  (XBUF_OFF + 32768)    // 81920

template<int MODE>
__global__ __launch_bounds__(256, 2) void gemm_mma(
    const __half* __restrict__ A, const __half* __restrict__ B,
    const float* __restrict__ bias,
    const __half* __restrict__ X,
    __half* __restrict__ Oh, float* __restrict__ Of,
    int M, int N, int Kd)
{
    extern __shared__ __align__(128) char smem[];
    const uint32_t sb = smem_u32(smem);

    const int tid  = threadIdx.x;
    const int lane = tid & 31;
    const int wid  = tid >> 5;
    const int warp_m = wid & 3;
    const int warp_n = wid >> 2;
    const int m0 = blockIdx.y * 128;
    const int n0 = blockIdx.x * 128;

    const int lr = tid >> 2;
    const int lc = tid & 3;

    float acc[2][8][4];
    #pragma unroll
    for (int a = 0; a < 2; a++)
        #pragma unroll
        for (int b = 0; b < 8; b++)
            #pragma unroll
            for (int c = 0; c < 4; c++) acc[a][b][c] = 0.f;

    const int grp = lane >> 3, r8 = lane & 7;
    const int rowoff = ((grp & 1) << 3) + r8;
    const int cg = grp >> 1;
    int offA[2], swA[2], offB[4], swB[4];
    #pragma unroll
    for (int tm = 0; tm < 2; tm++) {
        int r = warp_m * 32 + tm * 16 + rowoff;
        offA[tm] = r * 64; swA[tm] = (r >> 1) & 3;
    }
    #pragma unroll
    for (int p = 0; p < 4; p++) {
        int r = warp_n * 64 + p * 16 + rowoff;
        offB[p] = r * 64; swB[p] = (r >> 1) & 3;
    }

    const int NIT = Kd >> 5;

    auto load_stage = [&](int st, int k0) {
        uint32_t stb = sb + st * STAGE_B;
        #pragma unroll
        for (int i = 0; i < 4; i++) {
            int plane = i >> 1;
            int r = ((i & 1) << 6) + lr;
            uint32_t dst = stb + plane * 8192 + r * 64 + ((lc ^ ((r >> 1) & 3)) << 4);
            const char* src = (plane == 0)
                ? (const char*)(A + (size_t)(m0 + r) * Kd + k0 + lc * 8)
                : (const char*)(B + (size_t)(n0 + r) * Kd + k0 + lc * 8);
            cp_async16(dst, src);
        }
    };

    #pragma unroll
    for (int s = 0; s < NSTAGE; s++) {
        load_stage(s, s * 32);
        CP_COMMIT();
    }

    for (int it = 0; it < NIT; it++) {
        CP_WAIT2();
        __syncthreads();
        const int st = it % NSTAGE;
        const uint32_t stb = sb + st * STAGE_B;

        #pragma unroll
        for (int ks = 0; ks < 2; ks++) {
            uint32_t ah[2][4], bh[4][4];
            #pragma unroll
            for (int tm = 0; tm < 2; tm++) {
                uint32_t colA = (uint32_t)((((ks << 1) | cg) ^ swA[tm]) << 4);
                ldm_x4(ah[tm], stb + offA[tm] + colA);
            }
            #pragma unroll
            for (int p = 0; p < 4; p++) {
                uint32_t colB = (uint32_t)((((ks << 1) | cg) ^ swB[p]) << 4);
                ldm_x4(bh[p], stb + 8192 + offB[p] + colB);
            }
            #pragma unroll
            for (int tm = 0; tm < 2; tm++)
                #pragma unroll
                for (int tn = 0; tn < 8; tn++) {
                    int p = tn >> 1, o = tn & 1;
                    mma16816(acc[tm][tn], ah[tm], bh[p][o], bh[p][2 + o]);
                }
        }
        __syncthreads();

        int nxt = it + NSTAGE;
        if (nxt < NIT) load_stage(st, nxt * 32);
        if (MODE == 2 && it < 8) {
            // ride 4KB of the X tile per iter: 2048 chunks total = 128 rows x 16 chunks
            int idx = it * 256 + tid;
            int row = idx >> 4;       // 0..127 across 8 iters
            int c16 = idx & 15;       // 16B chunk within 256B row
            cp_async16(sb + XBUF_OFF + row * 256 + c16 * 16,
                       (const char*)(X + (size_t)(m0 + row) * N + n0 + c16 * 8));
        }
        CP_COMMIT();
    }

    if (MODE == 2) {
        CP_WAIT0();
        __syncthreads();
    }

    // ---------------- epilogue ----------------
    const int qr = lane >> 2;
    const int qc = (lane & 3) * 2;
    #pragma unroll
    for (int tm = 0; tm < 2; tm++) {
        int mb = m0 + warp_m * 32 + tm * 16;
        #pragma unroll
        for (int tn = 0; tn < 8; tn++) {
            int n = n0 + warp_n * 64 + tn * 8 + qc;
            float bx = bias[n], by = bias[n + 1];
            #pragma unroll
            for (int half = 0; half < 2; half++) {
                int m = mb + qr + half * 8;
                float vx = acc[tm][tn][half * 2 + 0] + bx;
                float vy = acc[tm][tn][half * 2 + 1] + by;
                size_t o = (size_t)m * N + n;
                if (MODE == 1) {
                    __half2 w;
                    w.x = __float2half(fmaxf(vx, 0.f));
                    w.y = __float2half(fmaxf(vy, 0.f));
                    *(__half2*)(Oh + o) = w;
                } else if (MODE == 2) {
                    float sx = 1.f / (1.f + __expf(-vx));
                    float sy = 1.f / (1.f + __expf(-vy));
                    __half2 tv = *(__half2*)(smem + XBUF_OFF + (m - m0) * 256 + (n - n0) * 2);
                    __half2 w;
                    w.x = __float2half(__half2float(tv.x) * sx);
                    w.y = __float2half(__half2float(tv.y) * sy);
                    *(__half2*)(Oh + o) = w;
                } else {
                    float2 w; w.x = vx; w.y = vy;
                    *(float2*)(Of + o) = w;
                }
            }
        }
    }
}

// ---------------- host launch ----------------
extern "C" void kernel_launch(void* const* d_in, const int* in_sizes, int n_in,
                              void* d_out, int out_size)
{
    const float* x  = (const float*)d_in[0];
    const float* W1 = (const float*)d_in[1];
    const float* b1 = (const float*)d_in[2];
    const float* W2 = (const float*)d_in[3];
    const float* b2 = (const float*)d_in[4];
    const float* W3 = (const float*)d_in[5];
    const float* b3 = (const float*)d_in[6];
    float* out = (float*)d_out;

    __half *pt, *ph, *pp, *w1, *w2, *w3;
    cudaGetSymbolAddress((void**)&pt, g_t);
    cudaGetSymbolAddress((void**)&ph, g_h);
    cudaGetSymbolAddress((void**)&pp, g_p);
    cudaGetSymbolAddress((void**)&w1, g_w1);
    cudaGetSymbolAddress((void**)&w2, g_w2);
    cudaGetSymbolAddress((void**)&w3, g_w3);

    cudaFuncSetAttribute(gemm_mma<1>, cudaFuncAttributeMaxDynamicSharedMemorySize, SMEM_BYTES);
    cudaFuncSetAttribute(gemm_mma<2>, cudaFuncAttributeMaxDynamicSharedMemorySize, SMEM2_BYTES);
    cudaFuncSetAttribute(gemm_mma<3>, cudaFuncAttributeMaxDynamicSharedMemorySize, SMEM_BYTES);

    unfold_tiled<<<dim3(4, 56, 8), 256>>>(x, pt);
    wtrans_all<<<3 * 1152, 256>>>(W1, W2, W3, w1, w2, w3);

    // K1: h = relu(t @ W1 + b1)        [25088 x 256],  K=2304
    gemm_mma<1><<<dim3(CDIM / 128, L_TOTAL / 128), 256, SMEM_BYTES>>>(
        pt, w1, b1, nullptr, ph, nullptr, L_TOTAL, CDIM, DDIM);
    // K2: p = t * sigmoid(h @ W2 + b2) [25088 x 2304], K=256 — X prefetched to smem
    gemm_mma<2><<<dim3(DDIM / 128, L_TOTAL / 128), 256, SMEM2_BYTES>>>(
        ph, w2, b2, pt, pp, nullptr, L_TOTAL, DDIM, CDIM);
    // K3: out = p @ W3 + b3            [25088 x 256],  K=2304
    gemm_mma<3><<<dim3(CDIM / 128, L_TOTAL / 128), 256, SMEM_BYTES>>>(
        pp, w3, b3, nullptr, nullptr, out, L_TOTAL, CDIM, DDIM);
}